// round 2
// baseline (speedup 1.0000x reference)
#include <cuda_runtime.h>

// DfOp: complex order-5 causal FIR on first 96 freq bins, copy the rest.
// spec: (B=8, T=3000, F=481, 2) f32
// coef: (B=8, T=3000, NDF=96, 2*NO=10) f32
//
// Strategy: minimize LSU instruction count (co-binding with DRAM) by using
// 16-byte loads/stores wherever the float2 index parity allows. Parity is
// uniform per (row, tap-row), so the float4-vs-2xfloat2 branches never
// diverge within a warp.

#define B_DIM 8
#define T_DIM 3000
#define F_DIM 481
#define NDF 96
#define NO 5

__global__ __launch_bounds__(256) void df_kernel(
    const float* __restrict__ spec,
    const float* __restrict__ coef,
    float* __restrict__ out)
{
    const int bt = blockIdx.x;            // 0 .. B*T-1
    const int t  = bt % T_DIM;
    const bool oddRow = (bt & 1);

    const float2* __restrict__ spec2 = reinterpret_cast<const float2*>(spec);
    const float4* __restrict__ spec4 = reinterpret_cast<const float4*>(spec);
    float2* __restrict__ out2 = reinterpret_cast<float2*>(out);
    float4* __restrict__ out4 = reinterpret_cast<float4*>(out);

    const size_t row = (size_t)bt * F_DIM;   // row start, in float2 units
    const int tid = threadIdx.x;

    if (tid < NDF / 2) {
        // ---- DF path: this thread computes bins j and j+1 ----
        const int j = tid * 2;

        // coef for 2 bins = 20 contiguous floats = 80 B, 16B-aligned for even j:
        // byte offset = (bt*96 + j)*40 ; bt*3840 % 16 == 0, j*40 % 16 == 0.
        const float4* __restrict__ c4 =
            reinterpret_cast<const float4*>(coef + ((size_t)bt * NDF + j) * (2 * NO));
        const float4 a = c4[0], b = c4[1], c = c4[2], d = c4[3], e = c4[4];
        // bin j:   cr = f0..f4, ci = f5..f9
        // bin j+1: cr = f10..f14, ci = f15..f19
        const float cr0[NO] = {a.x, a.y, a.z, a.w, b.x};
        const float ci0[NO] = {b.y, b.z, b.w, c.x, c.y};
        const float cr1[NO] = {c.z, c.w, d.x, d.y, d.z};
        const float ci1[NO] = {d.w, e.x, e.y, e.z, e.w};

        float fr0 = 0.f, fi0 = 0.f, fr1 = 0.f, fi1 = 0.f;
        #pragma unroll
        for (int k = 0; k < NO; ++k) {
            const int tapT = t - (NO - 1) + k;   // causal tap within batch
            float4 x = make_float4(0.f, 0.f, 0.f, 0.f);
            if (tapT >= 0) {
                const size_t i2 = (size_t)(bt - (NO - 1) + k) * F_DIM + j; // float2 idx
                if ((i2 & 1) == 0) {                    // 16B-aligned (uniform branch)
                    x = spec4[i2 >> 1];
                } else {
                    const float2 lo = spec2[i2];
                    const float2 hi = spec2[i2 + 1];
                    x = make_float4(lo.x, lo.y, hi.x, hi.y);
                }
            }
            fr0 += x.x * cr0[k] - x.y * ci0[k];
            fi0 += x.x * ci0[k] + x.y * cr0[k];
            fr1 += x.z * cr1[k] - x.w * ci1[k];
            fi1 += x.z * ci1[k] + x.w * cr1[k];
        }

        const size_t o2 = row + j;
        if ((o2 & 1) == 0) {                            // uniform per row
            out4[o2 >> 1] = make_float4(fr0, fi0, fr1, fi1);
        } else {
            out2[o2]     = make_float2(fr0, fi0);
            out2[o2 + 1] = make_float2(fr1, fi1);
        }
    } else if (tid < 48 + 193) {
        // ---- Copy path: bins [96, 481) = 385 float2 = 192 float4 + 1 float2 ----
        const int i = tid - 48;
        if (i < 192) {
            // even rows: pairs start at f=96 (aligned); odd rows: start at f=97
            const int f = (oddRow ? 97 : 96) + 2 * i;
            const size_t i2 = row + f;                  // even by construction
            out4[i2 >> 1] = spec4[i2 >> 1];
        } else {
            const int f = oddRow ? 96 : 480;            // the leftover scalar float2
            out2[row + f] = spec2[row + f];
        }
    }
}

extern "C" void kernel_launch(void* const* d_in, const int* in_sizes, int n_in,
                              void* d_out, int out_size)
{
    const float* spec = (const float*)d_in[0];
    const float* coef = (const float*)d_in[1];
    float* out        = (float*)d_out;

    df_kernel<<<B_DIM * T_DIM, 256>>>(spec, coef, out);
}